// round 15
// baseline (speedup 1.0000x reference)
#include <cuda_runtime.h>
#include <cuda_fp16.h>
#include <cstdint>

// Problem: B=16384, D=1024, T=512
// out[b,t] = (x@Wb + bb) + cumsum_t( relu(x@Wh^T + bh) )
// FP16 HMMA, 512 threads / 16 warps, warp tile 32x64. r11 base (86.2us) with
// TWO k-chunks per barrier interval: one wait+sync+bar per 128 k-elems.
// 4-stage B ring (sync before issue), 4-deep A conv ring, converts
// interleaved between MMA kk-blocks. Epilogue: 32-col strips, scan inlined
// with carry. r14 crash fix: HPITCH 34 -> 36 (row pitch must be 16B-aligned
// for the float4 scan/store paths).

#define D_DIM 1024
#define T_DIM 512
#define BM    128
#define BN    256
#define BK    64
#define THREADS 512
#define HPITCH 36             // floats per 32-col strip row (144B, 16B-aligned)

// ---- global scratch ----
__device__ __half g_wh[T_DIM * D_DIM];

// ---- smem layout (bytes) ----
#define SM_BH    0                       // 512 f (2048)
#define SM_WB    2048                    // 1024 f (4096)
#define SM_CARRY 6144                    // 128 f (512)
#define SM_RED   6656                    // 512 f (2048)
#define SM_CONV  8704                    // 4 groups x 4 bufs x 4096 = 65536
#define SM_BSTG  74240                   // 4 stages x 32768 = 131072
#define SM_HAZ   205312                  // 128*36*4 = 18432
#define SMEM_TOTAL 223744

// ---------------- helpers ----------------
__device__ __forceinline__ uint32_t smem_u32(const void* p) {
    uint32_t a;
    asm("{ .reg .u64 t; cvta.to.shared.u64 t, %1; cvt.u32.u64 %0, t; }" : "=r"(a) : "l"(p));
    return a;
}
__device__ __forceinline__ uint32_t swz128(uint32_t o) { return o ^ ((o >> 3) & 0x70); }

#define CP16(dst, src) \
    asm volatile("cp.async.cg.shared.global [%0], [%1], 16;" :: "r"(dst), "l"(src) : "memory")
#define CP_COMMIT() asm volatile("cp.async.commit_group;" ::: "memory")
#define CP_WAIT0()  asm volatile("cp.async.wait_group 0;" ::: "memory")
#define GROUP_BAR(id) \
    asm volatile("bar.sync %0, 128;" :: "r"(id) : "memory")

__device__ __forceinline__ void ldsm4(uint32_t* r, uint32_t addr) {
    asm volatile("ldmatrix.sync.aligned.m8n8.x4.shared.b16 {%0,%1,%2,%3}, [%4];"
                 : "=r"(r[0]), "=r"(r[1]), "=r"(r[2]), "=r"(r[3]) : "r"(addr));
}
__device__ __forceinline__ void mma16816(float* d, const uint32_t* a, const uint32_t* b) {
    asm volatile(
        "mma.sync.aligned.m16n8k16.row.col.f32.f16.f16.f32 "
        "{%0,%1,%2,%3}, {%4,%5,%6,%7}, {%8,%9}, {%0,%1,%2,%3};"
        : "+f"(d[0]), "+f"(d[1]), "+f"(d[2]), "+f"(d[3])
        : "r"(a[0]), "r"(a[1]), "r"(a[2]), "r"(a[3]), "r"(b[0]), "r"(b[1]));
}
__device__ __forceinline__ uint32_t pk2h(float a, float b) {
    __half2 h = __floats2half2_rn(a, b);
    return *(uint32_t*)&h;
}

// -------- prologue: convert Wh to fp16 --------
__global__ __launch_bounds__(256)
void wh_conv_kernel(const float* __restrict__ Wh) {
    int i = (blockIdx.x * 256 + threadIdx.x) * 4;
    float4 w = *(const float4*)(Wh + i);
    uint2 v = { pk2h(w.x, w.y), pk2h(w.z, w.w) };
    *(uint2*)((char*)g_wh + (size_t)i * 2) = v;
}

// -------- main fused kernel --------
__global__ __launch_bounds__(THREADS, 1)
void fused_kernel(const float* __restrict__ X,
                  const float* __restrict__ bh,
                  const float* __restrict__ Wb,
                  const float* __restrict__ bb,
                  float* __restrict__ out) {
    extern __shared__ char sm[];
    const uint32_t su = smem_u32(sm);
    const int tid = threadIdx.x;
    const int lane = tid & 31;
    const int wid = tid >> 5;
    const int g = wid >> 2;         // warprow group 0..3 -> m *32
    const int warpcol = wid & 3;    // 0..3 -> n *64
    const int bm = blockIdx.x * BM;

    float* sbh = (float*)(sm + SM_BH);
    float* swb = (float*)(sm + SM_WB);
    float* scarry = (float*)(sm + SM_CARRY);
    float* sred = (float*)(sm + SM_RED);
    float* shz = (float*)(sm + SM_HAZ);       // [128][HPITCH]

    for (int i = tid; i < T_DIM; i += THREADS) sbh[i] = bh[i];
    for (int i = tid; i < D_DIM; i += THREADS) swb[i] = Wb[i];
    const float bbv = bb[0];
    __syncthreads();

    // ---- conversion mapping: group g owns A rows 32g..32g+31 ----
    const int gt = tid & 127;
    const int cr = gt >> 2;          // row in group (0..31)
    const int cq = gt & 3;           // 16-col quarter of the 64-col chunk
    const float* xrow = X + (size_t)(bm + 32 * g + cr) * D_DIM + cq * 16;
    const uint32_t cdst0 = (uint32_t)cr * 128 + (((uint32_t)(2 * cq) << 4) ^ (((uint32_t)cr & 7) << 4));
    const uint32_t convg = SM_CONV + g * 16384;     // 4 bufs x 4096

    // ---- ldsm fragment address components (128B rows, SW128) ----
    const uint32_t xmask = ((uint32_t)lane & 7) << 4;
    const uint32_t a_rowoff = ((uint32_t)lane & 15) * 128;
    const uint32_t a_l16 = (((uint32_t)lane >> 4) & 1) * 16;
    const uint32_t b_rowoff = ((uint32_t)(warpcol * 64 + (lane & 7) + ((lane >> 4) & 1) * 8)) * 128;
    const uint32_t b_l16 = (((uint32_t)lane >> 3) & 1) * 16;

    // ---- B cp.async mapping: 2048 segs, 4/thread ----
    const int bseg = tid * 4;

    float v[16];
    float pbase = 0.0f;
    float acc[64];
#pragma unroll
    for (int j = 0; j < 64; j++) acc[j] = 0.0f;

    #define COMPUTE_KK(kk)                                                     \
    {                                                                          \
        const uint32_t akb = ((uint32_t)(kk) * 32 + a_l16) ^ xmask;            \
        const uint32_t bkb = ((uint32_t)(kk) * 32 + b_l16) ^ xmask;            \
        uint32_t bfr[4][4];                                                    \
        _Pragma("unroll")                                                      \
        for (int p = 0; p < 4; p++)                                            \
            ldsm4(bfr[p], sB + b_rowoff + p * 2048 + bkb);                     \
        _Pragma("unroll")                                                      \
        for (int mt = 0; mt < 2; mt++) {                                       \
            uint32_t af[4];                                                    \
            ldsm4(af, aB + a_rowoff + mt * 2048 + akb);                        \
            _Pragma("unroll")                                                  \
            for (int nt = 0; nt < 8; nt++) {                                   \
                float* d = acc + (mt * 8 + nt) * 4;                            \
                mma16816(d, af, &bfr[nt >> 1][(nt & 1) * 2]);                  \
            }                                                                  \
        }                                                                      \
    }

    #define ISSUE_B(ch)                                                        \
    {                                                                          \
        const int nci = (ch) >> 4;                                             \
        const int k0 = ((ch) & 15) * BK;                                       \
        const uint32_t sBo = su + SM_BSTG + ((ch) & 3) * 32768;                \
        _Pragma("unroll")                                                      \
        for (int q = 0; q < 4; q++) {                                          \
            int seg = bseg + q;                                                \
            int row = seg >> 3, cu = seg & 7;                                  \
            size_t gb = ((size_t)(nci * BN + row) * D_DIM + k0) * 2 + cu * 16; \
            CP16(sBo + swz128((uint32_t)(row * 128 + cu * 16)),                \
                 (const char*)g_wh + gb);                                      \
        }                                                                      \
        CP_COMMIT();                                                           \
    }

    #define LDG_X(ch)                                                          \
    {                                                                          \
        const float* xp = xrow + ((ch) & 15) * BK;                             \
        *(float4*)(v + 0)  = *(const float4*)(xp + 0);                         \
        *(float4*)(v + 4)  = *(const float4*)(xp + 4);                         \
        *(float4*)(v + 8)  = *(const float4*)(xp + 8);                         \
        *(float4*)(v + 12) = *(const float4*)(xp + 12);                        \
    }

    #define CONV_H0(ch)                                                        \
    {                                                                          \
        if ((ch) < 16) {                                                       \
            const float* wbp = swb + (ch) * BK + cq * 16;                      \
            _Pragma("unroll")                                                  \
            for (int j = 0; j < 8; j++) pbase = fmaf(v[j], wbp[j], pbase);     \
        }                                                                      \
        uint4 h0 = { pk2h(v[0], v[1]), pk2h(v[2], v[3]),                       \
                     pk2h(v[4], v[5]), pk2h(v[6], v[7]) };                     \
        *(uint4*)(sm + convg + ((ch) & 3) * 4096 + cdst0) = h0;                \
    }
    #define CONV_H1(ch)                                                        \
    {                                                                          \
        if ((ch) < 16) {                                                       \
            const float* wbp = swb + (ch) * BK + cq * 16;                      \
            _Pragma("unroll")                                                  \
            for (int j = 8; j < 16; j++) pbase = fmaf(v[j], wbp[j], pbase);    \
        }                                                                      \
        uint4 h1 = { pk2h(v[8], v[9]),  pk2h(v[10], v[11]),                    \
                     pk2h(v[12], v[13]), pk2h(v[14], v[15]) };                 \
        *(uint4*)(sm + convg + ((ch) & 3) * 4096 + (cdst0 ^ 16)) = h1;         \
    }

    // ---- prologue (super-iter 0): convert chunks 0,1; issue B 0,1 ----
    {
        LDG_X(0)
        ISSUE_B(0)
        ISSUE_B(1)
        CONV_H0(0)
        CONV_H1(0)
        LDG_X(1)
        CONV_H0(1)
        CONV_H1(1)
        GROUP_BAR(g + 1);
    }

    // ---- main loop: super-iters j=1..16, compute chunks 2j-2, 2j-1 ----
#pragma unroll 1
    for (int j = 1; j <= 16; j++) {
        const int ca = 2 * j - 2;
        const int cb = 2 * j - 1;
        const int cca = 2 * j;            // chunks converted this super-iter
        const int ccb = 2 * j + 1;

        CP_WAIT0();                       // B for ca, cb landed
        __syncthreads();                  // all warps done reading target stages
        if (j < 16) { ISSUE_B(cca) ISSUE_B(ccb) }

        // ---- chunk a ----
        {
            const uint32_t aB = su + convg + (ca & 3) * 4096;
            const uint32_t sB = su + SM_BSTG + (ca & 3) * 32768;
            COMPUTE_KK(0)
            if (j < 16) LDG_X(cca)
            COMPUTE_KK(1)
            if (j < 16) CONV_H0(cca)
            COMPUTE_KK(2)
            if (j < 16) CONV_H1(cca)
            COMPUTE_KK(3)
        }
        if (j < 16) LDG_X(ccb)
        // ---- chunk b ----
        {
            const uint32_t aB = su + convg + (cb & 3) * 4096;
            const uint32_t sB = su + SM_BSTG + (cb & 3) * 32768;
            COMPUTE_KK(0)
            if (j < 16) CONV_H0(ccb)
            COMPUTE_KK(1)
            if (j < 16) CONV_H1(ccb)
            COMPUTE_KK(2)
            COMPUTE_KK(3)
        }

        GROUP_BAR(g + 1);

        // ---- nc boundary epilogue (cb == 15 or 31) ----
        if (cb == 15 || cb == 31) {
            const int nc = cb >> 4;
            if (nc == 0) {
                __syncthreads();
                sred[tid] = pbase;
                __syncthreads();
                if (tid < BM) {
                    int o = (tid >> 5) * 128 + (tid & 31) * 4;
                    scarry[tid] = sred[o] + sred[o + 1] + sred[o + 2] + sred[o + 3] + bbv;
                }
            }
#pragma unroll 1
            for (int q = 0; q < 8; q++) {      // 32-col strips
                __syncthreads();
                if (warpcol == (q >> 1)) {
                    const int ntb = (q & 1) * 4;
#pragma unroll
                    for (int mt = 0; mt < 2; mt++)
#pragma unroll
                        for (int nt = 0; nt < 4; nt++) {
                            const float* d = acc + (mt * 8 + ntb + nt) * 4;
                            int r0 = g * 32 + mt * 16 + (lane >> 2);
                            int c0 = nt * 8 + 2 * (lane & 3);
                            int cg = nc * BN + q * 32 + c0;
                            float b0 = sbh[cg], b1 = sbh[cg + 1];
                            shz[r0 * HPITCH + c0]           = fmaxf(d[0] + b0, 0.0f);
                            shz[r0 * HPITCH + c0 + 1]       = fmaxf(d[1] + b1, 0.0f);
                            shz[(r0 + 8) * HPITCH + c0]     = fmaxf(d[2] + b0, 0.0f);
                            shz[(r0 + 8) * HPITCH + c0 + 1] = fmaxf(d[3] + b1, 0.0f);
                        }
                }
                __syncthreads();
                // inline scan with carry: 1 thread per row, 32 cols
                if (tid < BM) {
                    float run = scarry[tid];
                    float4* rp = (float4*)(shz + tid * HPITCH);
#pragma unroll
                    for (int jj = 0; jj < 8; jj++) {
                        float4 v4 = rp[jj];
                        v4.x += run; v4.y += v4.x; v4.z += v4.y; v4.w += v4.z;
                        run = v4.w;
                        rp[jj] = v4;
                    }
                    scarry[tid] = run;
                }
                __syncthreads();
                // coalesced store: 1024 float4, 2/thread
#pragma unroll
                for (int it = 0; it < 2; it++) {
                    int idx = it * 512 + tid;
                    int row = idx >> 3;
                    int c4 = (idx & 7) * 4;
                    const float* rp = shz + row * HPITCH + c4;
                    float4 o = { rp[0], rp[1], rp[2], rp[3] };
                    *(float4*)(out + (size_t)(bm + row) * T_DIM + nc * BN + q * 32 + c4) = o;
                }
            }
            if (nc == 0) {
#pragma unroll
                for (int jj = 0; jj < 64; jj++) acc[jj] = 0.0f;
            }
        }
    }
    #undef COMPUTE_KK
    #undef ISSUE_B
    #undef LDG_X
    #undef CONV_H0
    #undef CONV_H1
}

extern "C" void kernel_launch(void* const* d_in, const int* in_sizes, int n_in,
                              void* d_out, int out_size) {
    const float* x  = (const float*)d_in[0];
    const float* Wh = (const float*)d_in[1];
    const float* bh = (const float*)d_in[2];
    const float* Wb = (const float*)d_in[3];
    const float* bb = (const float*)d_in[4];
    float* out = (float*)d_out;

    const int B = in_sizes[0] / D_DIM;   // 16384

    cudaFuncSetAttribute(fused_kernel,
                         cudaFuncAttributeMaxDynamicSharedMemorySize, SMEM_TOTAL);

    wh_conv_kernel<<<(T_DIM * D_DIM) / 1024, 256>>>(Wh);
    fused_kernel<<<B / BM, THREADS, SMEM_TOTAL>>>(x, bh, Wb, bb, out);
}